// round 8
// baseline (speedup 1.0000x reference)
#include <cuda_runtime.h>
#include <cuda_bf16.h>

// FeaturesLinear: out[seg] = sum_{t in seg} weight[ids[t]] * ratings[t] + bias
// Sorted segs => each segment is a contiguous token range. One warp per
// output segment: binary search the range, gather+accumulate, store once.

#define DIM 16

// Weight gather: L2 evict_last cache-hint (keep table resident across replays).
__device__ __forceinline__ float4 ldg_wt(const float4* p, unsigned long long pol) {
    float4 v;
    asm("ld.global.nc.L2::cache_hint.v4.f32 {%0,%1,%2,%3}, [%4], %5;"
        : "=f"(v.x), "=f"(v.y), "=f"(v.z), "=f"(v.w)
        : "l"(p), "l"(pol));
    return v;
}

__global__ __launch_bounds__(256)
void fl_seg(const int*    __restrict__ ids,
            const float*  __restrict__ ratings,
            const int*    __restrict__ segs,
            const float4* __restrict__ weight4,
            const float4* __restrict__ bias4,
            float4*       __restrict__ out4,
            int n, int batch) {
    const int warpId = blockIdx.x * (blockDim.x >> 5) + (threadIdx.x >> 5);
    if (warpId >= batch) return;
    const int seg  = warpId;
    const int lane = threadIdx.x & 31;
    const int slot = lane & 3;      // which float4 of the 16-float row
    const int tg   = lane >> 2;     // token-group 0..7

    unsigned long long pol;
    asm("createpolicy.fractional.L2::evict_last.b64 %0, 1.0;" : "=l"(pol));

    // Uniform binary searches (all lanes follow identical path; probes broadcast).
    int lo, hi;
    {
        int l = 0, r = n;
        while (l < r) { int m = (l + r) >> 1; if (__ldg(&segs[m]) < seg) l = m + 1; else r = m; }
        lo = l;
        r = n;
        while (l < r) { int m = (l + r) >> 1; if (__ldg(&segs[m]) < seg + 1) l = m + 1; else r = m; }
        hi = l;
    }

    float4 acc = make_float4(0.f, 0.f, 0.f, 0.f);

    // Unrolled by 4: 4 independent id loads + 4 independent gathers in flight.
    int t = lo + tg;
    for (; t + 24 < hi; t += 32) {
        const int i0 = __ldg(&ids[t]);
        const int i1 = __ldg(&ids[t +  8]);
        const int i2 = __ldg(&ids[t + 16]);
        const int i3 = __ldg(&ids[t + 24]);
        const float r0 = __ldg(&ratings[t]);
        const float r1 = __ldg(&ratings[t +  8]);
        const float r2 = __ldg(&ratings[t + 16]);
        const float r3 = __ldg(&ratings[t + 24]);
        const float4 w0 = ldg_wt(&weight4[(size_t)i0 * 4 + slot], pol);
        const float4 w1 = ldg_wt(&weight4[(size_t)i1 * 4 + slot], pol);
        const float4 w2 = ldg_wt(&weight4[(size_t)i2 * 4 + slot], pol);
        const float4 w3 = ldg_wt(&weight4[(size_t)i3 * 4 + slot], pol);
        acc.x += w0.x * r0; acc.y += w0.y * r0; acc.z += w0.z * r0; acc.w += w0.w * r0;
        acc.x += w1.x * r1; acc.y += w1.y * r1; acc.z += w1.z * r1; acc.w += w1.w * r1;
        acc.x += w2.x * r2; acc.y += w2.y * r2; acc.z += w2.z * r2; acc.w += w2.w * r2;
        acc.x += w3.x * r3; acc.y += w3.y * r3; acc.z += w3.z * r3; acc.w += w3.w * r3;
    }
    for (; t < hi; t += 8) {
        const int   i = __ldg(&ids[t]);
        const float r = __ldg(&ratings[t]);
        const float4 w = ldg_wt(&weight4[(size_t)i * 4 + slot], pol);
        acc.x += w.x * r; acc.y += w.y * r; acc.z += w.z * r; acc.w += w.w * r;
    }

    // Whole warp is one segment: unconditional tree-sum over the 8 token-groups.
    #pragma unroll
    for (int off = 4; off <= 16; off <<= 1) {
        acc.x += __shfl_down_sync(0xffffffffu, acc.x, off);
        acc.y += __shfl_down_sync(0xffffffffu, acc.y, off);
        acc.z += __shfl_down_sync(0xffffffffu, acc.z, off);
        acc.w += __shfl_down_sync(0xffffffffu, acc.w, off);
    }

    // Lanes 0..3 hold the slot totals: add bias, single coalesced store.
    if (tg == 0) {
        const float4 b = __ldg(&bias4[slot]);
        float4 o;
        o.x = acc.x + b.x; o.y = acc.y + b.y;
        o.z = acc.z + b.z; o.w = acc.w + b.w;
        out4[(size_t)seg * 4 + slot] = o;
    }
}

extern "C" void kernel_launch(void* const* d_in, const int* in_sizes, int n_in,
                              void* d_out, int out_size) {
    const int*   ids     = (const int*)  d_in[0];
    const float* ratings = (const float*)d_in[1];
    const int*   segs    = (const int*)  d_in[2];
    // d_in[3] = batch_size scalar (device; batch derived from out_size instead)
    const float* weight  = (const float*)d_in[4];
    const float* bias    = (const float*)d_in[5];

    const int n     = in_sizes[0];
    const int batch = out_size / DIM;

    const int warpsPerBlock = 8;               // 256 threads
    const int blocks = (batch + warpsPerBlock - 1) / warpsPerBlock;
    fl_seg<<<blocks, 256>>>(ids, ratings, segs,
                            (const float4*)weight, (const float4*)bias,
                            (float4*)d_out, n, batch);
}

// round 9
// speedup vs baseline: 1.7975x; 1.7975x over previous
#include <cuda_runtime.h>
#include <cuda_bf16.h>

// FeaturesLinear: out[seg] = sum_t (weight[ids[t]] * ratings[t]) + bias
// ids: int32[N], ratings: f32[N], segs: int32[N] (sorted), weight: f32[V,16],
// bias: f32[16], out: f32[batch,16].  N = 819200 (multiple of 32).

#define DIM 16
#define T_PER_THREAD 4   // tokens per thread

// Weight gather: L2 evict_last cache-hint (table stays L2-resident across
// graph replays). L1 policy unchanged.
__device__ __forceinline__ float4 ldg_wt(const float4* p, unsigned long long pol) {
    float4 v;
    asm("ld.global.nc.L2::cache_hint.v4.f32 {%0,%1,%2,%3}, [%4], %5;"
        : "=f"(v.x), "=f"(v.y), "=f"(v.z), "=f"(v.w)
        : "l"(p), "l"(pol));
    return v;
}
// Meta loads: L2 evict_first hint, L1 caching preserved (broadcast lanes hit L1).
__device__ __forceinline__ int4 ldg_meta_i4(const int4* p, unsigned long long pol) {
    int4 v;
    asm("ld.global.nc.L2::cache_hint.v4.u32 {%0,%1,%2,%3}, [%4], %5;"
        : "=r"(v.x), "=r"(v.y), "=r"(v.z), "=r"(v.w)
        : "l"(p), "l"(pol));
    return v;
}
__device__ __forceinline__ float4 ldg_meta_f4(const float4* p, unsigned long long pol) {
    float4 v;
    asm("ld.global.nc.L2::cache_hint.v4.f32 {%0,%1,%2,%3}, [%4], %5;"
        : "=f"(v.x), "=f"(v.y), "=f"(v.z), "=f"(v.w)
        : "l"(p), "l"(pol));
    return v;
}
// One-instruction float4 global reduction (sm_100+).
__device__ __forceinline__ void red_add_v4(float* o, float4 v) {
    asm volatile("red.global.v4.f32.add [%0], {%1,%2,%3,%4};"
                 :: "l"(o), "f"(v.x), "f"(v.y), "f"(v.z), "f"(v.w) : "memory");
}

__global__ void fl_init_out(float4* __restrict__ out,
                            const float4* __restrict__ bias4,
                            int out_quads) {
    int i = blockIdx.x * blockDim.x + threadIdx.x;
    if (i < out_quads) out[i] = __ldg(&bias4[i & 3]);
}

// Lane layout: slot = lane & 3 (which float4 of the 16-float row),
// tokGroup = lane >> 2 (0..7). Thread handles 4 consecutive tokens;
// a warp covers 32 consecutive tokens.
__global__ __launch_bounds__(256)
void fl_main(const int*   __restrict__ ids,
             const float* __restrict__ ratings,
             const int*   __restrict__ segs,
             const float4* __restrict__ weight4,
             float*       __restrict__ out,
             int n) {
    const int lane     = threadIdx.x & 31;
    const int slot     = lane & 3;
    const int tokGroup = lane >> 2;
    const int warpsPerBlock = blockDim.x >> 5;
    const int warpId   = blockIdx.x * warpsPerBlock + (threadIdx.x >> 5);

    const int base = warpId * 32 + tokGroup * T_PER_THREAD;
    if (base >= n) return;

    unsigned long long polWt, polMeta;
    asm("createpolicy.fractional.L2::evict_last.b64 %0, 1.0;"  : "=l"(polWt));
    asm("createpolicy.fractional.L2::evict_first.b64 %0, 1.0;" : "=l"(polMeta));

    // ---- metadata for 4 tokens (L1-cached broadcast; L2 evict_first)
    int4   idv = ldg_meta_i4((const int4*)  (ids     + base), polMeta);
    float4 rv  = ldg_meta_f4((const float4*)(ratings + base), polMeta);
    int4   sv  = ldg_meta_i4((const int4*)  (segs    + base), polMeta);

    const int   id[4] = {idv.x, idv.y, idv.z, idv.w};
    const float r [4] = {rv.x,  rv.y,  rv.z,  rv.w};
    const int   sg[4] = {sv.x,  sv.y,  sv.z,  sv.w};

    // ---- issue all 4 independent row gathers up front (MLP = 4)
    float4 w[4];
    #pragma unroll
    for (int k = 0; k < T_PER_THREAD; k++)
        w[k] = ldg_wt(&weight4[(size_t)id[k] * 4 + slot], polWt);

    // ---- thread-serial accumulation with flush on segment boundary
    float4 acc;
    acc.x = w[0].x * r[0]; acc.y = w[0].y * r[0];
    acc.z = w[0].z * r[0]; acc.w = w[0].w * r[0];

    #pragma unroll
    for (int k = 1; k < T_PER_THREAD; k++) {
        if (sg[k] != sg[k - 1]) {
            red_add_v4(out + (size_t)sg[k - 1] * DIM + slot * 4, acc);
            acc.x = acc.y = acc.z = acc.w = 0.f;
        }
        acc.x += w[k].x * r[k]; acc.y += w[k].y * r[k];
        acc.z += w[k].z * r[k]; acc.w += w[k].w * r[k];
    }

    // ---- cross-lane segmented suffix reduction on trailing partials.
    // Trailing keys are monotone across the warp (sorted segs), so the
    // strided conditional add is an exact segmented reduction.
    int seg = sg[T_PER_THREAD - 1];
    #pragma unroll
    for (int off = 4; off <= 16; off <<= 1) {
        int   oseg = __shfl_down_sync(0xffffffffu, seg, off);
        float ox   = __shfl_down_sync(0xffffffffu, acc.x, off);
        float oy   = __shfl_down_sync(0xffffffffu, acc.y, off);
        float oz   = __shfl_down_sync(0xffffffffu, acc.z, off);
        float ow   = __shfl_down_sync(0xffffffffu, acc.w, off);
        if ((lane + off) < 32 && oseg == seg) {
            acc.x += ox; acc.y += oy; acc.z += oz; acc.w += ow;
        }
    }

    const int  pseg = __shfl_up_sync(0xffffffffu, seg, 4);
    const bool head = (tokGroup == 0) || (pseg != seg);

    if (head) {
        red_add_v4(out + (size_t)seg * DIM + slot * 4, acc);
    }
}

extern "C" void kernel_launch(void* const* d_in, const int* in_sizes, int n_in,
                              void* d_out, int out_size) {
    const int*   ids     = (const int*)  d_in[0];
    const float* ratings = (const float*)d_in[1];
    const int*   segs    = (const int*)  d_in[2];
    // d_in[3] = batch_size scalar (unused)
    const float* weight  = (const float*)d_in[4];
    const float* bias    = (const float*)d_in[5];
    float*       out     = (float*)d_out;

    const int n = in_sizes[0];

    // Init output with bias (vectorized).
    {
        int quads   = out_size / 4;
        int threads = 256;
        int blocks  = (quads + threads - 1) / threads;
        fl_init_out<<<blocks, threads>>>((float4*)out, (const float4*)bias, quads);
    }

    // Main gather + segmented reduce: 32 tokens per warp, 8 warps per block.
    {
        int warps   = (n + 31) / 32;
        int threads = 256;
        int blocks  = (warps + 7) / 8;
        fl_main<<<blocks, threads>>>(ids, ratings, segs,
                                     (const float4*)weight, out, n);
    }
}

// round 10
// speedup vs baseline: 1.8020x; 1.0025x over previous
#include <cuda_runtime.h>
#include <cuda_bf16.h>

// FeaturesLinear: out[seg] = sum_t (weight[ids[t]] * ratings[t]) + bias
// ids: int32[N], ratings: f32[N], segs: int32[N] (sorted), weight: f32[V,16],
// bias: f32[16], out: f32[batch,16].  N = 819200 (multiple of 32).

#define DIM 16
#define T_PER_THREAD 4   // tokens per thread

// Weight gather: L2 cache-hint, evict_last on a 0.75 fraction of accesses.
// Fraction < 1 keeps the protected set below the L2 persisting-way capacity
// so ~48MB of the 64MB table is STABLY retained across graph replays
// (fraction 1.0 thrashes the protected partition and retains ~nothing).
__device__ __forceinline__ float4 ldg_wt(const float4* p, unsigned long long pol) {
    float4 v;
    asm("ld.global.nc.L2::cache_hint.v4.f32 {%0,%1,%2,%3}, [%4], %5;"
        : "=f"(v.x), "=f"(v.y), "=f"(v.z), "=f"(v.w)
        : "l"(p), "l"(pol));
    return v;
}
// Meta loads: L2 evict_first hint, L1 caching preserved (broadcast lanes hit L1).
__device__ __forceinline__ int4 ldg_meta_i4(const int4* p, unsigned long long pol) {
    int4 v;
    asm("ld.global.nc.L2::cache_hint.v4.u32 {%0,%1,%2,%3}, [%4], %5;"
        : "=r"(v.x), "=r"(v.y), "=r"(v.z), "=r"(v.w)
        : "l"(p), "l"(pol));
    return v;
}
__device__ __forceinline__ float4 ldg_meta_f4(const float4* p, unsigned long long pol) {
    float4 v;
    asm("ld.global.nc.L2::cache_hint.v4.f32 {%0,%1,%2,%3}, [%4], %5;"
        : "=f"(v.x), "=f"(v.y), "=f"(v.z), "=f"(v.w)
        : "l"(p), "l"(pol));
    return v;
}
// One-instruction float4 global reduction (sm_100+).
__device__ __forceinline__ void red_add_v4(float* o, float4 v) {
    asm volatile("red.global.v4.f32.add [%0], {%1,%2,%3,%4};"
                 :: "l"(o), "f"(v.x), "f"(v.y), "f"(v.z), "f"(v.w) : "memory");
}

__global__ void fl_init_out(float4* __restrict__ out,
                            const float4* __restrict__ bias4,
                            int out_quads) {
    int i = blockIdx.x * blockDim.x + threadIdx.x;
    if (i < out_quads) out[i] = __ldg(&bias4[i & 3]);
}

// Lane layout: slot = lane & 3 (which float4 of the 16-float row),
// tokGroup = lane >> 2 (0..7). Thread handles 4 consecutive tokens;
// a warp covers 32 consecutive tokens.
__global__ __launch_bounds__(256)
void fl_main(const int*   __restrict__ ids,
             const float* __restrict__ ratings,
             const int*   __restrict__ segs,
             const float4* __restrict__ weight4,
             float*       __restrict__ out,
             int n) {
    const int lane     = threadIdx.x & 31;
    const int slot     = lane & 3;
    const int tokGroup = lane >> 2;
    const int warpsPerBlock = blockDim.x >> 5;
    const int warpId   = blockIdx.x * warpsPerBlock + (threadIdx.x >> 5);

    const int base = warpId * 32 + tokGroup * T_PER_THREAD;
    if (base >= n) return;

    unsigned long long polWt, polMeta;
    asm("createpolicy.fractional.L2::evict_last.b64 %0, 0.75;"  : "=l"(polWt));
    asm("createpolicy.fractional.L2::evict_first.b64 %0, 1.0;" : "=l"(polMeta));

    // ---- metadata for 4 tokens (L1-cached broadcast; L2 evict_first)
    int4   idv = ldg_meta_i4((const int4*)  (ids     + base), polMeta);
    float4 rv  = ldg_meta_f4((const float4*)(ratings + base), polMeta);
    int4   sv  = ldg_meta_i4((const int4*)  (segs    + base), polMeta);

    const int   id[4] = {idv.x, idv.y, idv.z, idv.w};
    const float r [4] = {rv.x,  rv.y,  rv.z,  rv.w};
    const int   sg[4] = {sv.x,  sv.y,  sv.z,  sv.w};

    // ---- issue all 4 independent row gathers up front (MLP = 4)
    float4 w[4];
    #pragma unroll
    for (int k = 0; k < T_PER_THREAD; k++)
        w[k] = ldg_wt(&weight4[(size_t)id[k] * 4 + slot], polWt);

    // ---- thread-serial accumulation with flush on segment boundary
    float4 acc;
    acc.x = w[0].x * r[0]; acc.y = w[0].y * r[0];
    acc.z = w[0].z * r[0]; acc.w = w[0].w * r[0];

    #pragma unroll
    for (int k = 1; k < T_PER_THREAD; k++) {
        if (sg[k] != sg[k - 1]) {
            red_add_v4(out + (size_t)sg[k - 1] * DIM + slot * 4, acc);
            acc.x = acc.y = acc.z = acc.w = 0.f;
        }
        acc.x += w[k].x * r[k]; acc.y += w[k].y * r[k];
        acc.z += w[k].z * r[k]; acc.w += w[k].w * r[k];
    }

    // ---- cross-lane segmented suffix reduction on trailing partials.
    // Trailing keys are monotone across the warp (sorted segs), so the
    // strided conditional add is an exact segmented reduction.
    int seg = sg[T_PER_THREAD - 1];
    #pragma unroll
    for (int off = 4; off <= 16; off <<= 1) {
        int   oseg = __shfl_down_sync(0xffffffffu, seg, off);
        float ox   = __shfl_down_sync(0xffffffffu, acc.x, off);
        float oy   = __shfl_down_sync(0xffffffffu, acc.y, off);
        float oz   = __shfl_down_sync(0xffffffffu, acc.z, off);
        float ow   = __shfl_down_sync(0xffffffffu, acc.w, off);
        if ((lane + off) < 32 && oseg == seg) {
            acc.x += ox; acc.y += oy; acc.z += oz; acc.w += ow;
        }
    }

    const int  pseg = __shfl_up_sync(0xffffffffu, seg, 4);
    const bool head = (tokGroup == 0) || (pseg != seg);

    if (head) {
        red_add_v4(out + (size_t)seg * DIM + slot * 4, acc);
    }
}

extern "C" void kernel_launch(void* const* d_in, const int* in_sizes, int n_in,
                              void* d_out, int out_size) {
    const int*   ids     = (const int*)  d_in[0];
    const float* ratings = (const float*)d_in[1];
    const int*   segs    = (const int*)  d_in[2];
    // d_in[3] = batch_size scalar (unused)
    const float* weight  = (const float*)d_in[4];
    const float* bias    = (const float*)d_in[5];
    float*       out     = (float*)d_out;

    const int n = in_sizes[0];

    // Init output with bias (vectorized).
    {
        int quads   = out_size / 4;
        int threads = 256;
        int blocks  = (quads + threads - 1) / threads;
        fl_init_out<<<blocks, threads>>>((float4*)out, (const float4*)bias, quads);
    }

    // Main gather + segmented reduce: 32 tokens per warp, 8 warps per block.
    {
        int warps   = (n + 31) / 32;
        int threads = 256;
        int blocks  = (warps + 7) / 8;
        fl_main<<<blocks, threads>>>(ids, ratings, segs,
                                     (const float4*)weight, out, n);
    }
}